// round 1
// baseline (speedup 1.0000x reference)
#include <cuda_runtime.h>

#define D        128
#define MAXN     100000
#define MAXE     1600000
#define TM       64
#define GTHREADS 256
#define WS_STRIDE 132   // padded row stride for transposed W in smem (128 + 4)

// -------- device scratch (no allocations allowed) --------
__device__ float g_h[MAXN * D];     // post-GEMM, normalized, *norm_out
__device__ float g_agg[MAXN * D];   // scatter destination
__device__ int   g_degO[MAXN];
__device__ int   g_degI[MAXN];
__device__ float g_nO[MAXN];        // rsqrt(max(deg_out,1))
__device__ float g_nI[MAXN];        // rsqrt(max(deg_in,1))

// -------- degree / norms --------
__global__ void zero_deg_k(int n) {
    int i = blockIdx.x * blockDim.x + threadIdx.x;
    if (i < n) { g_degO[i] = 0; g_degI[i] = 0; }
}

__global__ void degree_k(const int* __restrict__ src, const int* __restrict__ dst, int E) {
    int e = blockIdx.x * blockDim.x + threadIdx.x;
    if (e < E) {
        atomicAdd(&g_degO[src[e]], 1);
        atomicAdd(&g_degI[dst[e]], 1);
    }
}

__global__ void norm_k(int n) {
    int i = blockIdx.x * blockDim.x + threadIdx.x;
    if (i < n) {
        g_nO[i] = rsqrtf(fmaxf((float)g_degO[i], 1.0f));
        g_nI[i] = rsqrtf(fmaxf((float)g_degI[i], 1.0f));
    }
}

__global__ void zero_agg_k(int n4) {
    int i = blockIdx.x * blockDim.x + threadIdx.x;
    if (i < n4) ((float4*)g_agg)[i] = make_float4(0.f, 0.f, 0.f, 0.f);
}

// -------- fused GEMM + bias + L2-normalize*1.8 + *norm_out --------
// Hout[n,:] = normalize(X[n,:] (*rin[n]) @ W^T + b) * 1.8 * g_nO[n]
__global__ void __launch_bounds__(GTHREADS, 2)
gemm_norm_k(const float* __restrict__ X,
            const float* __restrict__ W,
            const float* __restrict__ b,
            const float* __restrict__ rin,   // null for layer 1
            float* __restrict__ Hout,
            int N)
{
    extern __shared__ float sm[];
    float* ws = sm;                    // [D][WS_STRIDE], ws[k*WS_STRIDE + c] = W[c][k]
    float* xs = sm + D * WS_STRIDE;    // [TM][D]
    const int tid = threadIdx.x;
    const int nb  = blockIdx.x * TM;

    // Load + transpose W (one time per block)
    for (int i = tid; i < D * D; i += GTHREADS) {
        int c = i >> 7, k = i & (D - 1);
        ws[k * WS_STRIDE + c] = W[i];          // W row-major [c][k]
    }
    // Load X tile (optionally scaled by rin = norm_in)
    for (int i = tid; i < TM * D; i += GTHREADS) {
        int n = i >> 7;
        int node = nb + n;
        float v = 0.f;
        if (node < N) {
            int k = i & (D - 1);
            v = X[(size_t)node * D + k];
            if (rin) v *= rin[node];
        }
        xs[i] = v;
    }
    __syncthreads();

    const int cg = tid & 31;           // col group (lane)
    const int c0 = cg * 4;
    const int n0 = (tid >> 5) * 8;     // 8 nodes per thread

    float acc[8][4];
    #pragma unroll
    for (int i = 0; i < 8; i++) { acc[i][0]=0.f; acc[i][1]=0.f; acc[i][2]=0.f; acc[i][3]=0.f; }

    #pragma unroll 8
    for (int k = 0; k < D; k++) {
        const float4 w = *(const float4*)&ws[k * WS_STRIDE + c0];
        #pragma unroll
        for (int i = 0; i < 8; i++) {
            const float xv = xs[(n0 + i) * D + k];
            acc[i][0] += xv * w.x;
            acc[i][1] += xv * w.y;
            acc[i][2] += xv * w.z;
            acc[i][3] += xv * w.w;
        }
    }

    const float4 bb = *(const float4*)&b[c0];
    #pragma unroll
    for (int i = 0; i < 8; i++) {
        acc[i][0] += bb.x; acc[i][1] += bb.y; acc[i][2] += bb.z; acc[i][3] += bb.w;
        // row sum-of-squares: partial over this lane's 4 cols, butterfly over 32 lanes
        float s = acc[i][0]*acc[i][0] + acc[i][1]*acc[i][1]
                + acc[i][2]*acc[i][2] + acc[i][3]*acc[i][3];
        #pragma unroll
        for (int off = 16; off; off >>= 1) s += __shfl_xor_sync(0xffffffffu, s, off);
        const int node = nb + n0 + i;
        if (node < N) {
            const float sc = 1.8f / fmaxf(sqrtf(s), 1e-12f) * g_nO[node];
            float4 o;
            o.x = acc[i][0] * sc; o.y = acc[i][1] * sc;
            o.z = acc[i][2] * sc; o.w = acc[i][3] * sc;
            *(float4*)&Hout[(size_t)node * D + c0] = o;
        }
    }
}

// -------- edge scatter: agg[dst] += h[src], one warp per edge --------
__global__ void scatter_k(const float* __restrict__ h,
                          const int* __restrict__ src,
                          const int* __restrict__ dst,
                          float* __restrict__ agg,
                          int E)
{
    unsigned gid = blockIdx.x * blockDim.x + threadIdx.x;
    unsigned e = gid >> 5;
    if (e >= (unsigned)E) return;
    const int j = (gid & 31) * 4;
    const int s = src[e];
    const int d = dst[e];
    const float4 v = *(const float4*)&h[(size_t)s * D + j];
    float* p = &agg[(size_t)d * D + j];
    asm volatile("red.global.add.v4.f32 [%0], {%1, %2, %3, %4};"
                 :: "l"(p), "f"(v.x), "f"(v.y), "f"(v.z), "f"(v.w)
                 : "memory");
}

// -------- out = agg * norm_in --------
__global__ void finalize_k(float* __restrict__ out, int N) {
    unsigned gid = blockIdx.x * blockDim.x + threadIdx.x;
    if (gid >= (unsigned)N * 32u) return;
    const unsigned row = gid >> 5;
    const float sc = g_nI[row];
    float4 v = ((const float4*)g_agg)[gid];
    v.x *= sc; v.y *= sc; v.z *= sc; v.w *= sc;
    ((float4*)out)[gid] = v;
}

extern "C" void kernel_launch(void* const* d_in, const int* in_sizes, int n_in,
                              void* d_out, int out_size)
{
    const float* x   = (const float*)d_in[0];
    const float* W1  = (const float*)d_in[1];
    const float* b1  = (const float*)d_in[2];
    const float* W2  = (const float*)d_in[3];
    const float* b2  = (const float*)d_in[4];
    const int*   src = (const int*)d_in[5];
    const int*   dst = (const int*)d_in[6];
    float* out = (float*)d_out;

    const int N = in_sizes[0] / D;
    const int E = in_sizes[5];

    float *h_ptr, *agg_ptr, *nI_ptr;
    cudaGetSymbolAddress((void**)&h_ptr,   g_h);
    cudaGetSymbolAddress((void**)&agg_ptr, g_agg);
    cudaGetSymbolAddress((void**)&nI_ptr,  g_nI);

    const int SMEM_BYTES = (D * WS_STRIDE + TM * D) * (int)sizeof(float);  // 100352
    cudaFuncSetAttribute(gemm_norm_k, cudaFuncAttributeMaxDynamicSharedMemorySize, SMEM_BYTES);

    const int nBlkGemm = (N + TM - 1) / TM;
    const int nThrNode = (N + 255) / 256;
    const int nThrEdge = (E + 255) / 256;
    const int n4       = N * 32;                 // N*128/4 float4s
    const int nThrN4   = (n4 + 255) / 256;
    const int nThrScat = ((E * 32) + 255) / 256; // one warp per edge

    // degree + norms
    zero_deg_k<<<nThrNode, 256>>>(N);
    degree_k<<<nThrEdge, 256>>>(src, dst, E);
    norm_k<<<nThrNode, 256>>>(N);

    // layer 1
    gemm_norm_k<<<nBlkGemm, GTHREADS, SMEM_BYTES>>>(x, W1, b1, nullptr, h_ptr, N);
    zero_agg_k<<<nThrN4, 256>>>(n4);
    scatter_k<<<nThrScat, 256>>>(h_ptr, src, dst, agg_ptr, E);

    // layer 2 (norm_in folded into GEMM input load)
    gemm_norm_k<<<nBlkGemm, GTHREADS, SMEM_BYTES>>>(agg_ptr, W2, b2, nI_ptr, h_ptr, N);
    zero_agg_k<<<nThrN4, 256>>>(n4);
    scatter_k<<<nThrScat, 256>>>(h_ptr, src, dst, agg_ptr, E);

    // out = agg * norm_in
    finalize_k<<<nThrN4, 256>>>(out, N);
}

// round 2
// speedup vs baseline: 1.8397x; 1.8397x over previous
#include <cuda_runtime.h>

#define D        128
#define MAXN     100000
#define MAXE     1600000
#define TM       64
#define GTHREADS 256
#define WS_STRIDE 132   // padded row stride for transposed W in smem (128 + 4)
#define SCAN_T   256

// -------- device scratch (no allocations allowed) --------
__device__ float g_h[MAXN * D];       // post-GEMM, normalized, *norm_out
__device__ float g_agg[MAXN * D];     // layer-1 aggregated output (input to layer 2)
__device__ int   g_degO[MAXN];
__device__ int   g_degI[MAXN];
__device__ float g_nO[MAXN];          // rsqrt(max(deg_out,1))
__device__ float g_nI[MAXN];          // rsqrt(max(deg_in,1))
__device__ int   g_rowptr[MAXN + 1];  // CSR (by dst)
__device__ int   g_esrc[MAXE];        // CSR column indices (src node per edge)
__device__ int   g_bsum[512];
__device__ int   g_fill[MAXN];

// -------- f32x2 packed-FMA helpers (sm_103a FFMA2) --------
__device__ __forceinline__ unsigned long long fma2(unsigned long long a,
                                                   unsigned long long b,
                                                   unsigned long long c) {
    unsigned long long d;
    asm("fma.rn.f32x2 %0, %1, %2, %3;" : "=l"(d) : "l"(a), "l"(b), "l"(c));
    return d;
}
__device__ __forceinline__ unsigned long long splat2(float x) {
    unsigned long long d;
    asm("mov.b64 %0, {%1, %1};" : "=l"(d) : "f"(x));
    return d;
}
__device__ __forceinline__ void unpack2(unsigned long long v, float& lo, float& hi) {
    asm("mov.b64 {%0, %1}, %2;" : "=f"(lo), "=f"(hi) : "l"(v));
}

// -------- degree / norms --------
__global__ void zero_deg_k(int n) {
    int i = blockIdx.x * blockDim.x + threadIdx.x;
    if (i < n) { g_degO[i] = 0; g_degI[i] = 0; g_fill[i] = 0; }
}

__global__ void degree_k(const int* __restrict__ src, const int* __restrict__ dst, int E) {
    int e = blockIdx.x * blockDim.x + threadIdx.x;
    if (e < E) {
        atomicAdd(&g_degO[src[e]], 1);
        atomicAdd(&g_degI[dst[e]], 1);
    }
}

__global__ void norm_k(int n) {
    int i = blockIdx.x * blockDim.x + threadIdx.x;
    if (i < n) {
        g_nO[i] = rsqrtf(fmaxf((float)g_degO[i], 1.0f));
        g_nI[i] = rsqrtf(fmaxf((float)g_degI[i], 1.0f));
    }
}

// -------- prefix scan (3 kernels) to build rowptr from degI --------
__global__ void scan_block_k(int n) {
    __shared__ int s[SCAN_T];
    int i = blockIdx.x * SCAN_T + threadIdx.x;
    int v = (i < n) ? g_degI[i] : 0;
    s[threadIdx.x] = v;
    __syncthreads();
    #pragma unroll
    for (int off = 1; off < SCAN_T; off <<= 1) {
        int t = (threadIdx.x >= off) ? s[threadIdx.x - off] : 0;
        __syncthreads();
        s[threadIdx.x] += t;
        __syncthreads();
    }
    if (i < n) g_rowptr[i + 1] = s[threadIdx.x];   // block-local inclusive
    if (threadIdx.x == SCAN_T - 1) g_bsum[blockIdx.x] = s[SCAN_T - 1];
}

__global__ void scan_bsum_k(int nb) {   // single block of 512
    __shared__ int s[512];
    int v = (threadIdx.x < nb) ? g_bsum[threadIdx.x] : 0;
    s[threadIdx.x] = v;
    __syncthreads();
    #pragma unroll
    for (int off = 1; off < 512; off <<= 1) {
        int t = (threadIdx.x >= off) ? s[threadIdx.x - off] : 0;
        __syncthreads();
        s[threadIdx.x] += t;
        __syncthreads();
    }
    if (threadIdx.x < nb) g_bsum[threadIdx.x] = s[threadIdx.x] - v;  // exclusive
}

__global__ void scan_add_k(int n) {
    int i = blockIdx.x * SCAN_T + threadIdx.x;
    if (i < n) g_rowptr[i + 1] += g_bsum[blockIdx.x];
    if (i == 0) g_rowptr[0] = 0;
}

__global__ void fill_k(const int* __restrict__ src, const int* __restrict__ dst, int E) {
    int e = blockIdx.x * blockDim.x + threadIdx.x;
    if (e < E) {
        int d = dst[e];
        int pos = g_rowptr[d] + atomicAdd(&g_fill[d], 1);
        g_esrc[pos] = src[e];
    }
}

// -------- fused GEMM + bias + L2-normalize*1.8 + *norm_out (FFMA2 inner loop) --------
// Hout[n,:] = normalize(X[n,:] @ W^T + b) * 1.8 * g_nO[n]
__global__ void __launch_bounds__(GTHREADS, 2)
gemm_norm_k(const float* __restrict__ X,
            const float* __restrict__ W,
            const float* __restrict__ b,
            float* __restrict__ Hout,
            int N)
{
    extern __shared__ float sm[];
    float* ws = sm;                    // [D][WS_STRIDE], ws[k*WS_STRIDE + c] = W[c][k]
    float* xs = sm + D * WS_STRIDE;    // [TM][D]
    const int tid = threadIdx.x;
    const int nb  = blockIdx.x * TM;

    // Load + transpose W
    for (int i = tid; i < D * D; i += GTHREADS) {
        int c = i >> 7, k = i & (D - 1);
        ws[k * WS_STRIDE + c] = W[i];
    }
    // Load X tile
    for (int i = tid; i < TM * D; i += GTHREADS) {
        int n = i >> 7;
        int node = nb + n;
        xs[i] = (node < N) ? X[(size_t)node * D + (i & (D - 1))] : 0.f;
    }
    __syncthreads();

    const int cg = tid & 31;
    const int c0 = cg * 4;             // 4 consecutive output cols per lane
    const int n0 = (tid >> 5) * 8;     // 8 nodes per thread

    // acc2[i][p]: packed pair of accumulators, p=0 -> cols (c0,c0+1), p=1 -> (c0+2,c0+3)
    unsigned long long acc2[8][2];
    #pragma unroll
    for (int i = 0; i < 8; i++) { acc2[i][0] = 0ull; acc2[i][1] = 0ull; }

    #pragma unroll 4
    for (int k4 = 0; k4 < D / 4; k4++) {
        // 4 rows of transposed W: each float4 = cols c0..c0+3 for one k value
        ulonglong2 wq0 = *(const ulonglong2*)&ws[(4 * k4 + 0) * WS_STRIDE + c0];
        ulonglong2 wq1 = *(const ulonglong2*)&ws[(4 * k4 + 1) * WS_STRIDE + c0];
        ulonglong2 wq2 = *(const ulonglong2*)&ws[(4 * k4 + 2) * WS_STRIDE + c0];
        ulonglong2 wq3 = *(const ulonglong2*)&ws[(4 * k4 + 3) * WS_STRIDE + c0];
        #pragma unroll
        for (int i = 0; i < 8; i++) {
            const float4 xv = *(const float4*)&xs[(n0 + i) * D + 4 * k4];
            unsigned long long x0 = splat2(xv.x);
            unsigned long long x1 = splat2(xv.y);
            unsigned long long x2 = splat2(xv.z);
            unsigned long long x3 = splat2(xv.w);
            acc2[i][0] = fma2(x0, wq0.x, acc2[i][0]);
            acc2[i][1] = fma2(x0, wq0.y, acc2[i][1]);
            acc2[i][0] = fma2(x1, wq1.x, acc2[i][0]);
            acc2[i][1] = fma2(x1, wq1.y, acc2[i][1]);
            acc2[i][0] = fma2(x2, wq2.x, acc2[i][0]);
            acc2[i][1] = fma2(x2, wq2.y, acc2[i][1]);
            acc2[i][0] = fma2(x3, wq3.x, acc2[i][0]);
            acc2[i][1] = fma2(x3, wq3.y, acc2[i][1]);
        }
    }

    const float4 bb = *(const float4*)&b[c0];
    #pragma unroll
    for (int i = 0; i < 8; i++) {
        float a0, a1, a2, a3;
        unpack2(acc2[i][0], a0, a1);
        unpack2(acc2[i][1], a2, a3);
        a0 += bb.x; a1 += bb.y; a2 += bb.z; a3 += bb.w;
        float s = a0 * a0 + a1 * a1 + a2 * a2 + a3 * a3;
        #pragma unroll
        for (int off = 16; off; off >>= 1) s += __shfl_xor_sync(0xffffffffu, s, off);
        const int node = nb + n0 + i;
        if (node < N) {
            const float sc = 1.8f / fmaxf(sqrtf(s), 1e-12f) * g_nO[node];
            float4 o;
            o.x = a0 * sc; o.y = a1 * sc; o.z = a2 * sc; o.w = a3 * sc;
            *(float4*)&Hout[(size_t)node * D + c0] = o;
        }
    }
}

// -------- CSR gather: out[d,:] = (sum_{e: dst=d} h[src_e,:]) * nI[d] --------
// One warp per dst node; lane owns 4 columns (float4).
__global__ void gather_k(const float* __restrict__ h,
                         float* __restrict__ out,
                         int N)
{
    const int node = blockIdx.x * 8 + (threadIdx.x >> 5);
    if (node >= N) return;
    const int lane = threadIdx.x & 31;
    const int j4 = lane * 4;
    const int start = g_rowptr[node];
    const int end   = g_rowptr[node + 1];

    float4 acc = make_float4(0.f, 0.f, 0.f, 0.f);

    for (int base = start; base < end; base += 32) {
        const int e = base + lane;
        const int s = (e < end) ? g_esrc[e] : 0;
        const int cnt = min(32, end - base);
        int j = 0;
        // unrolled by 4 for MLP
        for (; j + 4 <= cnt; j += 4) {
            int s0 = __shfl_sync(0xffffffffu, s, j + 0);
            int s1 = __shfl_sync(0xffffffffu, s, j + 1);
            int s2 = __shfl_sync(0xffffffffu, s, j + 2);
            int s3 = __shfl_sync(0xffffffffu, s, j + 3);
            float4 v0 = *(const float4*)&h[(size_t)s0 * D + j4];
            float4 v1 = *(const float4*)&h[(size_t)s1 * D + j4];
            float4 v2 = *(const float4*)&h[(size_t)s2 * D + j4];
            float4 v3 = *(const float4*)&h[(size_t)s3 * D + j4];
            acc.x += v0.x; acc.y += v0.y; acc.z += v0.z; acc.w += v0.w;
            acc.x += v1.x; acc.y += v1.y; acc.z += v1.z; acc.w += v1.w;
            acc.x += v2.x; acc.y += v2.y; acc.z += v2.z; acc.w += v2.w;
            acc.x += v3.x; acc.y += v3.y; acc.z += v3.z; acc.w += v3.w;
        }
        for (; j < cnt; j++) {
            int sj = __shfl_sync(0xffffffffu, s, j);
            float4 v = *(const float4*)&h[(size_t)sj * D + j4];
            acc.x += v.x; acc.y += v.y; acc.z += v.z; acc.w += v.w;
        }
    }

    const float sc = g_nI[node];
    acc.x *= sc; acc.y *= sc; acc.z *= sc; acc.w *= sc;
    *(float4*)&out[(size_t)node * D + j4] = acc;
}

extern "C" void kernel_launch(void* const* d_in, const int* in_sizes, int n_in,
                              void* d_out, int out_size)
{
    const float* x   = (const float*)d_in[0];
    const float* W1  = (const float*)d_in[1];
    const float* b1  = (const float*)d_in[2];
    const float* W2  = (const float*)d_in[3];
    const float* b2  = (const float*)d_in[4];
    const int*   src = (const int*)d_in[5];
    const int*   dst = (const int*)d_in[6];
    float* out = (float*)d_out;

    const int N = in_sizes[0] / D;
    const int E = in_sizes[5];

    float *h_ptr, *agg_ptr;
    cudaGetSymbolAddress((void**)&h_ptr,   g_h);
    cudaGetSymbolAddress((void**)&agg_ptr, g_agg);

    const int SMEM_BYTES = (D * WS_STRIDE + TM * D) * (int)sizeof(float);
    cudaFuncSetAttribute(gemm_norm_k, cudaFuncAttributeMaxDynamicSharedMemorySize, SMEM_BYTES);

    const int nBlkGemm   = (N + TM - 1) / TM;
    const int nBlkNode   = (N + 255) / 256;
    const int nBlkEdge   = (E + 255) / 256;
    const int nBlkScan   = (N + SCAN_T - 1) / SCAN_T;
    const int nBlkGather = (N + 7) / 8;

    // degrees, norms, CSR build (once; used by both layers)
    zero_deg_k<<<nBlkNode, 256>>>(N);
    degree_k<<<nBlkEdge, 256>>>(src, dst, E);
    norm_k<<<nBlkNode, 256>>>(N);
    scan_block_k<<<nBlkScan, SCAN_T>>>(N);
    scan_bsum_k<<<1, 512>>>(nBlkScan);
    scan_add_k<<<nBlkScan, SCAN_T>>>(N);
    fill_k<<<nBlkEdge, 256>>>(src, dst, E);

    // layer 1: gemm(x) -> g_h ; gather -> g_agg (norm_in applied)
    gemm_norm_k<<<nBlkGemm, GTHREADS, SMEM_BYTES>>>(x, W1, b1, h_ptr, N);
    gather_k<<<nBlkGather, 256>>>(h_ptr, agg_ptr, N);

    // layer 2: gemm(g_agg) -> g_h ; gather -> out (norm_in applied)
    gemm_norm_k<<<nBlkGemm, GTHREADS, SMEM_BYTES>>>(agg_ptr, W2, b2, h_ptr, N);
    gather_k<<<nBlkGather, 256>>>(h_ptr, out, N);
}

// round 4
// speedup vs baseline: 1.9669x; 1.0691x over previous
#include <cuda_runtime.h>
#include <cuda_fp16.h>
#include <cstdint>

#define D        128
#define MAXN     100000
#define MAXE     1600000
#define TM       64
#define GTHREADS 256
#define WS_STRIDE 132   // padded row stride for transposed W in smem (128 + 4)
#define SCAN_T   256

// -------- device scratch --------
__device__ __half g_h[MAXN * D];      // post-GEMM h, fp16 (gather is sole consumer)
__device__ float  g_agg[MAXN * D];    // layer-1 aggregate (fp32, feeds GEMM2)
__device__ int    g_degO[MAXN];
__device__ int    g_degI[MAXN];
__device__ float  g_nO[MAXN];
__device__ float  g_nI[MAXN];
__device__ int    g_rowptr[MAXN + 1];
__device__ int    g_esrc[MAXE];
__device__ int    g_bsum[512];
__device__ int    g_fill[MAXN + 1];   // CSR fill cursor (pre-seeded with rowptr)

// -------- f32x2 packed-FMA helpers (sm_103a FFMA2) --------
__device__ __forceinline__ unsigned long long fma2(unsigned long long a,
                                                   unsigned long long b,
                                                   unsigned long long c) {
    unsigned long long d;
    asm("fma.rn.f32x2 %0, %1, %2, %3;" : "=l"(d) : "l"(a), "l"(b), "l"(c));
    return d;
}
__device__ __forceinline__ unsigned long long splat2(float x) {
    unsigned long long d;
    asm("mov.b64 %0, {%1, %1};" : "=l"(d) : "f"(x));
    return d;
}
__device__ __forceinline__ void unpack2(unsigned long long v, float& lo, float& hi) {
    asm("mov.b64 {%0, %1}, %2;" : "=f"(lo), "=f"(hi) : "l"(v));
}

// -------- degree --------
__global__ void zero_deg_k(int n) {
    int i = blockIdx.x * blockDim.x + threadIdx.x;
    if (i < n) { g_degO[i] = 0; g_degI[i] = 0; }
}
__global__ void degree_k(const int* __restrict__ src, const int* __restrict__ dst, int E) {
    int e = blockIdx.x * blockDim.x + threadIdx.x;
    if (e < E) { atomicAdd(&g_degO[src[e]], 1); atomicAdd(&g_degI[dst[e]], 1); }
}

// -------- prefix scan to build rowptr from degI, fused norms + cursor init --------
__global__ void scan_block_k(int n) {
    __shared__ int s[SCAN_T];
    int i = blockIdx.x * SCAN_T + threadIdx.x;
    int v = (i < n) ? g_degI[i] : 0;
    s[threadIdx.x] = v;
    __syncthreads();
    #pragma unroll
    for (int off = 1; off < SCAN_T; off <<= 1) {
        int t = (threadIdx.x >= off) ? s[threadIdx.x - off] : 0;
        __syncthreads();
        s[threadIdx.x] += t;
        __syncthreads();
    }
    if (i < n) g_rowptr[i + 1] = s[threadIdx.x];
    if (threadIdx.x == SCAN_T - 1) g_bsum[blockIdx.x] = s[SCAN_T - 1];
}
__global__ void scan_bsum_k(int nb) {
    __shared__ int s[512];
    int v = (threadIdx.x < nb) ? g_bsum[threadIdx.x] : 0;
    s[threadIdx.x] = v;
    __syncthreads();
    #pragma unroll
    for (int off = 1; off < 512; off <<= 1) {
        int t = (threadIdx.x >= off) ? s[threadIdx.x - off] : 0;
        __syncthreads();
        s[threadIdx.x] += t;
        __syncthreads();
    }
    if (threadIdx.x < nb) g_bsum[threadIdx.x] = s[threadIdx.x] - v;
}
__global__ void scan_add_norm_k(int n) {
    int i = blockIdx.x * SCAN_T + threadIdx.x;
    if (i < n) {
        int v = g_rowptr[i + 1] + g_bsum[blockIdx.x];
        g_rowptr[i + 1] = v;
        g_fill[i + 1]   = v;  // cursor seed
        g_nO[i] = rsqrtf(fmaxf((float)g_degO[i], 1.0f));
        g_nI[i] = rsqrtf(fmaxf((float)g_degI[i], 1.0f));
    }
    if (i == 0) { g_rowptr[0] = 0; g_fill[0] = 0; }
}
__global__ void fill_k(const int* __restrict__ src, const int* __restrict__ dst, int E) {
    int e = blockIdx.x * blockDim.x + threadIdx.x;
    if (e < E) {
        int pos = atomicAdd(&g_fill[dst[e]], 1);
        g_esrc[pos] = src[e];
    }
}

// -------- fused GEMM + bias + L2-normalize*1.8 + *norm_out (FFMA2), fp16 output --------
__global__ void __launch_bounds__(GTHREADS, 2)
gemm_norm_k(const float* __restrict__ X,
            const float* __restrict__ W,
            const float* __restrict__ b,
            __half* __restrict__ Hout,
            int N)
{
    extern __shared__ float sm[];
    float* ws = sm;                    // ws[k*WS_STRIDE + c] = W[c][k]
    float* xs = sm + D * WS_STRIDE;    // [TM][D]
    const int tid = threadIdx.x;
    const int nb  = blockIdx.x * TM;

    for (int i = tid; i < D * D; i += GTHREADS) {
        int c = i >> 7, k = i & (D - 1);
        ws[k * WS_STRIDE + c] = W[i];
    }
    for (int i = tid; i < TM * D; i += GTHREADS) {
        int node = nb + (i >> 7);
        xs[i] = (node < N) ? X[(size_t)node * D + (i & (D - 1))] : 0.f;
    }
    __syncthreads();

    const int cg = tid & 31;
    const int c0 = cg * 4;
    const int n0 = (tid >> 5) * 8;

    unsigned long long acc2[8][2];
    #pragma unroll
    for (int i = 0; i < 8; i++) { acc2[i][0] = 0ull; acc2[i][1] = 0ull; }

    #pragma unroll 4
    for (int k4 = 0; k4 < D / 4; k4++) {
        ulonglong2 wq0 = *(const ulonglong2*)&ws[(4 * k4 + 0) * WS_STRIDE + c0];
        ulonglong2 wq1 = *(const ulonglong2*)&ws[(4 * k4 + 1) * WS_STRIDE + c0];
        ulonglong2 wq2 = *(const ulonglong2*)&ws[(4 * k4 + 2) * WS_STRIDE + c0];
        ulonglong2 wq3 = *(const ulonglong2*)&ws[(4 * k4 + 3) * WS_STRIDE + c0];
        #pragma unroll
        for (int i = 0; i < 8; i++) {
            const float4 xv = *(const float4*)&xs[(n0 + i) * D + 4 * k4];
            unsigned long long x0 = splat2(xv.x);
            unsigned long long x1 = splat2(xv.y);
            unsigned long long x2 = splat2(xv.z);
            unsigned long long x3 = splat2(xv.w);
            acc2[i][0] = fma2(x0, wq0.x, acc2[i][0]);
            acc2[i][1] = fma2(x0, wq0.y, acc2[i][1]);
            acc2[i][0] = fma2(x1, wq1.x, acc2[i][0]);
            acc2[i][1] = fma2(x1, wq1.y, acc2[i][1]);
            acc2[i][0] = fma2(x2, wq2.x, acc2[i][0]);
            acc2[i][1] = fma2(x2, wq2.y, acc2[i][1]);
            acc2[i][0] = fma2(x3, wq3.x, acc2[i][0]);
            acc2[i][1] = fma2(x3, wq3.y, acc2[i][1]);
        }
    }

    const float4 bb = *(const float4*)&b[c0];
    #pragma unroll
    for (int i = 0; i < 8; i++) {
        float a0, a1, a2, a3;
        unpack2(acc2[i][0], a0, a1);
        unpack2(acc2[i][1], a2, a3);
        a0 += bb.x; a1 += bb.y; a2 += bb.z; a3 += bb.w;
        float s = a0 * a0 + a1 * a1 + a2 * a2 + a3 * a3;
        #pragma unroll
        for (int off = 16; off; off >>= 1) s += __shfl_xor_sync(0xffffffffu, s, off);
        const int node = nb + n0 + i;
        if (node < N) {
            const float sc = 1.8f / fmaxf(sqrtf(s), 1e-12f) * g_nO[node];
            __half2 h0 = __float22half2_rn(make_float2(a0 * sc, a1 * sc));
            __half2 h1 = __float22half2_rn(make_float2(a2 * sc, a3 * sc));
            uint2 o;
            o.x = *(uint32_t*)&h0;
            o.y = *(uint32_t*)&h1;
            *(uint2*)&Hout[(size_t)node * D + c0] = o;
        }
    }
}

// -------- CSR gather (fp16 h -> fp32 accumulate): out[d,:] = sum h[src,:] * nI[d] --------
__device__ __forceinline__ void acc_row(float4& acc, const __half* __restrict__ h,
                                        int s, int j4) {
    uint2 u = *(const uint2*)&h[(size_t)s * D + j4];
    __half2 p0 = *(__half2*)&u.x;
    __half2 p1 = *(__half2*)&u.y;
    float2 f0 = __half22float2(p0);
    float2 f1 = __half22float2(p1);
    acc.x += f0.x; acc.y += f0.y; acc.z += f1.x; acc.w += f1.y;
}

__global__ void gather_k(const __half* __restrict__ h,
                         float* __restrict__ out,
                         int N)
{
    const int node = blockIdx.x * 8 + (threadIdx.x >> 5);
    if (node >= N) return;
    const int lane = threadIdx.x & 31;
    const int j4 = lane * 4;
    const int start = g_rowptr[node];
    const int end   = g_rowptr[node + 1];

    float4 acc = make_float4(0.f, 0.f, 0.f, 0.f);

    for (int base = start; base < end; base += 32) {
        const int e = base + lane;
        const int s = (e < end) ? g_esrc[e] : 0;
        const int cnt = min(32, end - base);
        int j = 0;
        for (; j + 8 <= cnt; j += 8) {
            int s0 = __shfl_sync(0xffffffffu, s, j + 0);
            int s1 = __shfl_sync(0xffffffffu, s, j + 1);
            int s2 = __shfl_sync(0xffffffffu, s, j + 2);
            int s3 = __shfl_sync(0xffffffffu, s, j + 3);
            int s4 = __shfl_sync(0xffffffffu, s, j + 4);
            int s5 = __shfl_sync(0xffffffffu, s, j + 5);
            int s6 = __shfl_sync(0xffffffffu, s, j + 6);
            int s7 = __shfl_sync(0xffffffffu, s, j + 7);
            acc_row(acc, h, s0, j4); acc_row(acc, h, s1, j4);
            acc_row(acc, h, s2, j4); acc_row(acc, h, s3, j4);
            acc_row(acc, h, s4, j4); acc_row(acc, h, s5, j4);
            acc_row(acc, h, s6, j4); acc_row(acc, h, s7, j4);
        }
        for (; j + 2 <= cnt; j += 2) {
            int s0 = __shfl_sync(0xffffffffu, s, j + 0);
            int s1 = __shfl_sync(0xffffffffu, s, j + 1);
            acc_row(acc, h, s0, j4); acc_row(acc, h, s1, j4);
        }
        if (j < cnt) {
            int s0 = __shfl_sync(0xffffffffu, s, j);
            acc_row(acc, h, s0, j4);
        }
    }

    const float sc = g_nI[node];
    acc.x *= sc; acc.y *= sc; acc.z *= sc; acc.w *= sc;
    *(float4*)&out[(size_t)node * D + j4] = acc;
}

extern "C" void kernel_launch(void* const* d_in, const int* in_sizes, int n_in,
                              void* d_out, int out_size)
{
    const float* x   = (const float*)d_in[0];
    const float* W1  = (const float*)d_in[1];
    const float* b1  = (const float*)d_in[2];
    const float* W2  = (const float*)d_in[3];
    const float* b2  = (const float*)d_in[4];
    const int*   src = (const int*)d_in[5];
    const int*   dst = (const int*)d_in[6];
    float* out = (float*)d_out;

    const int N = in_sizes[0] / D;
    const int E = in_sizes[5];

    __half* h_ptr;
    float*  agg_ptr;
    cudaGetSymbolAddress((void**)&h_ptr,   g_h);
    cudaGetSymbolAddress((void**)&agg_ptr, g_agg);

    const int SMEM_BYTES = (D * WS_STRIDE + TM * D) * (int)sizeof(float);
    cudaFuncSetAttribute(gemm_norm_k, cudaFuncAttributeMaxDynamicSharedMemorySize, SMEM_BYTES);

    const int nBlkGemm   = (N + TM - 1) / TM;
    const int nBlkNode   = (N + 255) / 256;
    const int nBlkEdge   = (E + 255) / 256;
    const int nBlkScan   = (N + SCAN_T - 1) / SCAN_T;
    const int nBlkGather = (N + 7) / 8;

    // degrees, norms, CSR (once)
    zero_deg_k<<<nBlkNode, 256>>>(N);
    degree_k<<<nBlkEdge, 256>>>(src, dst, E);
    scan_block_k<<<nBlkScan, SCAN_T>>>(N);
    scan_bsum_k<<<1, 512>>>(nBlkScan);
    scan_add_norm_k<<<nBlkScan, SCAN_T>>>(N);
    fill_k<<<nBlkEdge, 256>>>(src, dst, E);

    // layer 1
    gemm_norm_k<<<nBlkGemm, GTHREADS, SMEM_BYTES>>>(x, W1, b1, h_ptr, N);
    gather_k<<<nBlkGather, 256>>>(h_ptr, agg_ptr, N);

    // layer 2
    gemm_norm_k<<<nBlkGemm, GTHREADS, SMEM_BYTES>>>(agg_ptr, W2, b2, h_ptr, N);
    gather_k<<<nBlkGather, 256>>>(h_ptr, out, N);
}